// round 17
// baseline (speedup 1.0000x reference)
#include <cuda_runtime.h>
#include <math.h>
#include <stdint.h>

#define T_STEPS 1024
#define BATCH   64
#define VDIM    256
#define HIDDEN  512
#define CPB     64                 // columns per CTA
#define BG      4                  // batches per group
#define CBLKS   8                  // CTAs per group
#define GROUPS  16                 // batch groups
#define NB      128                // CTAs
#define RT      256
#define PSTR    21                 // partials row stride (16 data + 5 pad)
#define REC_SMEM (120 * 1024)      // force 1 CTA/SM

// Scratch (device globals: allocation APIs are forbidden)
__device__ float g_P [(size_t)T_STEPS * BATCH * HIDDEN];
__device__ float g_S0[(size_t)T_STEPS * BATCH * HIDDEN];
__device__ float g_Hbuf[2][GROUPS][BG * HIDDEN];

// Per-CTA progress counters, each on its own 128B line.
// Semantics within one rnn_rec launch: v = number of publishes done by that
// CTA (1 after the h0 prologue, t+2 after publishing step t). Zeroed by
// rnn_reset before each rec launch (kernel boundary = device-wide sync).
struct PadC { unsigned v; unsigned pad[31]; };
__device__ PadC g_cnt[GROUPS][CBLKS];

// ---------------------------------------------------------------------------
__global__ void rnn_reset()
{
    int i = threadIdx.x;
    if (i < GROUPS * CBLKS) ((PadC*)g_cnt)[i].v = 0u;
}

// ---------------------------------------------------------------------------
// GEMM: C[m][n] = sum_k A[m][k]*W[n*ldw+k] + bias[n]  (exact R12 version)
// ---------------------------------------------------------------------------
__global__ __launch_bounds__(256) void gemm_awt(
    const float* __restrict__ A, const float* __restrict__ W,
    const float* __restrict__ bias, float* __restrict__ C,
    int K, int ldw)
{
    __shared__ float As[8][128];
    __shared__ float Ws[8][128];

    const int tid = threadIdx.x;
    const int m0 = blockIdx.y * 128;
    const int n0 = blockIdx.x * 128;
    const int tx = tid & 15;
    const int ty = tid >> 4;
    const int rowL = tid >> 1;
    const int colL = (tid & 1) * 4;

    const float* Ag = A + (size_t)(m0 + rowL) * K + colL;
    const float* Wg = W + (size_t)(n0 + rowL) * ldw + colL;

    float acc[8][8];
#pragma unroll
    for (int i = 0; i < 8; ++i)
#pragma unroll
        for (int j = 0; j < 8; ++j) acc[i][j] = 0.f;

    float4 av = *(const float4*)(Ag);
    float4 wv = *(const float4*)(Wg);

    for (int k0 = 0; k0 < K; k0 += 8) {
        __syncthreads();
        As[colL + 0][rowL] = av.x; As[colL + 1][rowL] = av.y;
        As[colL + 2][rowL] = av.z; As[colL + 3][rowL] = av.w;
        Ws[colL + 0][rowL] = wv.x; Ws[colL + 1][rowL] = wv.y;
        Ws[colL + 2][rowL] = wv.z; Ws[colL + 3][rowL] = wv.w;
        __syncthreads();
        if (k0 + 8 < K) {
            av = *(const float4*)(Ag + k0 + 8);
            wv = *(const float4*)(Wg + k0 + 8);
        }
#pragma unroll
        for (int k = 0; k < 8; ++k) {
            float a[8], b[8];
#pragma unroll
            for (int i = 0; i < 8; ++i) a[i] = As[k][ty * 8 + i];
#pragma unroll
            for (int j = 0; j < 8; ++j) b[j] = Ws[k][tx * 8 + j];
#pragma unroll
            for (int i = 0; i < 8; ++i)
#pragma unroll
                for (int j = 0; j < 8; ++j)
                    acc[i][j] += a[i] * b[j];
        }
    }

    float bn[8];
#pragma unroll
    for (int j = 0; j < 8; ++j) bn[j] = bias[n0 + tx * 8 + j];

    float* Cp = C + (size_t)(m0 + ty * 8) * HIDDEN + n0 + tx * 8;
#pragma unroll
    for (int i = 0; i < 8; ++i) {
        float4 v0, v1;
        v0.x = acc[i][0] + bn[0]; v0.y = acc[i][1] + bn[1];
        v0.z = acc[i][2] + bn[2]; v0.w = acc[i][3] + bn[3];
        v1.x = acc[i][4] + bn[4]; v1.y = acc[i][5] + bn[5];
        v1.z = acc[i][6] + bn[6]; v1.w = acc[i][7] + bn[7];
        *(float4*)(Cp + (size_t)i * HIDDEN)     = v0;
        *(float4*)(Cp + (size_t)i * HIDDEN + 4) = v1;
    }
}

// ---------------------------------------------------------------------------
// Persistent recurrence (R12 structure) with de-aggregated barrier:
//   producer: h STG -> __threadfence (ALL threads, parallel drain)
//             -> __syncthreads -> tid0 st.release.gpu of OWN counter.
//   consumer: batched ld.acquire.gpu poll of the 8 group counters.
// ---------------------------------------------------------------------------
__global__ __launch_bounds__(RT, 1) void rnn_rec(
    const float* __restrict__ P,
    const float* __restrict__ Wfull, int ldw, int koff,
    const float* __restrict__ h0,
    float* __restrict__ states,
    float* __restrict__ last)
{
    extern __shared__ float sh[];
    float* Ps = sh;                        // [256][PSTR]

    const int tid  = threadIdx.x;
    const int cblk = blockIdx.x & (CBLKS - 1);
    const int grp  = blockIdx.x >> 3;
    const int j0   = cblk * CPB;
    const int kc   = tid >> 4;             // 0..15 (uniform per half-warp)
    const int jg   = tid & 15;             // 0..15
    const int rb   = tid >> 6;             // reduce role: batch 0..3
    const int rcol = tid & 63;
    const int rj   = j0 + rcol;
    const int rbg  = grp * BG + rb;

    unsigned* mycnt = &g_cnt[grp][cblk].v;

    // Weights in registers: rows j0 + jg*4 + c, k = kc*32 .. +32.
    union LLF { float4 f; longlong2 l; };
    longlong2 wr[4][8];
#pragma unroll
    for (int c = 0; c < 4; ++c) {
        const float* wp = Wfull + (size_t)(j0 + jg * 4 + c) * ldw + koff + kc * 32;
#pragma unroll
        for (int i = 0; i < 8; ++i) {
            LLF u; u.f = *(const float4*)(wp + i * 4);
            wr[c][i] = u.l;
        }
    }

    // Prologue: publish our 64-col slice of h0 into buffer 1 (read at t=0).
    g_Hbuf[1][grp][rb * HIDDEN + rj] = h0[(size_t)rbg * HIDDEN + rj];
    __threadfence();
    __syncthreads();
    if (tid == 0)
        asm volatile("st.release.gpu.global.u32 [%0], %1;"
                     :: "l"(mycnt), "r"(1u) : "memory");

    for (int t = 0; t < T_STEPS; ++t) {
        float p = P[((size_t)t * BATCH + rbg) * HIDDEN + rj];  // before poll

        // Poll all 8 group counters (batched acquire loads -> ~1 RTT detect).
        {
            const unsigned need = (unsigned)(t + 1);
            for (;;) {
                unsigned v[CBLKS], mn = 0xffffffffu;
#pragma unroll
                for (int c = 0; c < CBLKS; ++c)
                    asm volatile("ld.acquire.gpu.global.u32 %0, [%1];"
                                 : "=r"(v[c]) : "l"(&g_cnt[grp][c].v) : "memory");
#pragma unroll
                for (int c = 0; c < CBLKS; ++c) mn = min(mn, v[c]);
                if (mn >= need) break;
            }
        }

        // h_{t-1} straight from L2 into registers; 2 batches at a time.
        const float* hc = &g_Hbuf[(t + 1) & 1][grp][kc * 32];
        long long acc[4][4];
#pragma unroll
        for (int c = 0; c < 4; ++c)
#pragma unroll
            for (int b = 0; b < 4; ++b) acc[c][b] = 0;

#pragma unroll
        for (int pr = 0; pr < 2; ++pr) {
            LLF h[2][8];
#pragma unroll
            for (int b = 0; b < 2; ++b)
#pragma unroll
                for (int i = 0; i < 8; ++i)
                    h[b][i].f = __ldcg((const float4*)(hc + (pr * 2 + b) * HIDDEN + i * 4));
#pragma unroll
            for (int i = 0; i < 8; ++i)
#pragma unroll
                for (int c = 0; c < 4; ++c) {
                    longlong2 w = wr[c][i];
                    asm("fma.rn.f32x2 %0, %1, %2, %0;"
                        : "+l"(acc[c][pr * 2 + 0]) : "l"(w.x), "l"(h[0][i].l.x));
                    asm("fma.rn.f32x2 %0, %1, %2, %0;"
                        : "+l"(acc[c][pr * 2 + 0]) : "l"(w.y), "l"(h[0][i].l.y));
                    asm("fma.rn.f32x2 %0, %1, %2, %0;"
                        : "+l"(acc[c][pr * 2 + 1]) : "l"(w.x), "l"(h[1][i].l.x));
                    asm("fma.rn.f32x2 %0, %1, %2, %0;"
                        : "+l"(acc[c][pr * 2 + 1]) : "l"(w.y), "l"(h[1][i].l.y));
                }
        }

        // Partials to smem: out o = b*64 + jg*4 + c.
#pragma unroll
        for (int c = 0; c < 4; ++c)
#pragma unroll
            for (int b = 0; b < 4; ++b) {
                float2 f = *reinterpret_cast<float2*>(&acc[c][b]);
                Ps[(b * 64 + jg * 4 + c) * PSTR + kc] = f.x + f.y;
            }
        __syncthreads();

        // Reduce: thread owns output (rb, rcol).
        float s = 0.f;
        const float* pr2 = Ps + tid * PSTR;
#pragma unroll
        for (int i = 0; i < 16; ++i) s += pr2[i];
        float hv = tanhf(p + s);

        if (t == T_STEPS - 1) {
            states[((size_t)t * BATCH + rbg) * HIDDEN + rj] = hv;
            last[(size_t)rbg * HIDDEN + rj] = hv;
            break;
        }

        // Publish h, signal own counter, THEN write states (off drain path).
        g_Hbuf[t & 1][grp][rb * HIDDEN + rj] = hv;
        __threadfence();     // parallel drain across all threads
        __syncthreads();     // h published CTA-wide; also protects Ps reuse
        if (tid == 0)
            asm volatile("st.release.gpu.global.u32 [%0], %1;"
                         :: "l"(mycnt), "r"((unsigned)(t + 2)) : "memory");
        states[((size_t)t * BATCH + rbg) * HIDDEN + rj] = hv;
    }
}

// ---------------------------------------------------------------------------
extern "C" void kernel_launch(void* const* d_in, const int* in_sizes, int n_in,
                              void* d_out, int out_size)
{
    (void)in_sizes; (void)n_in; (void)out_size;
    const float* inputs = (const float*)d_in[0];
    const float* H      = (const float*)d_in[1];
    const float* W_net  = (const float*)d_in[2];
    const float* b_net  = (const float*)d_in[3];
    const float* W_deep = (const float*)d_in[4];
    const float* b_deep = (const float*)d_in[5];

    float* out     = (float*)d_out;
    float* states1 = out;
    float* lasts   = out + (size_t)T_STEPS * BATCH * HIDDEN;

    float *P, *S0;
    cudaGetSymbolAddress((void**)&P,  g_P);
    cudaGetSymbolAddress((void**)&S0, g_S0);

    cudaFuncSetAttribute(rnn_rec, cudaFuncAttributeMaxDynamicSharedMemorySize, REC_SMEM);

    dim3 ggrid(HIDDEN / 128, (T_STEPS * BATCH) / 128);

    gemm_awt<<<ggrid, 256>>>(inputs, W_net, b_net, P, VDIM, VDIM + HIDDEN);
    rnn_reset<<<1, 128>>>();
    rnn_rec<<<NB, RT, REC_SMEM>>>(P, W_net, VDIM + HIDDEN, VDIM, H, S0, lasts);

    gemm_awt<<<ggrid, 256>>>(S0, W_deep, b_deep, P, HIDDEN, 2 * HIDDEN);
    rnn_reset<<<1, 128>>>();
    rnn_rec<<<NB, RT, REC_SMEM>>>(P, W_deep, 2 * HIDDEN, HIDDEN,
                                  H + BATCH * HIDDEN, states1,
                                  lasts + BATCH * HIDDEN);
}